// round 4
// baseline (speedup 1.0000x reference)
#include <cuda_runtime.h>
#include <cstdint>

// LWTA over groups of 4 consecutive fp32 units. One float4 == one pool group.
// Keep first max (strict > matches jnp.argmax first-tie), zero rest.
// Block-strided unroll-4, 512-thread blocks: every LDG.128/STG.128 fully
// coalesced (512B contiguous per warp), MLP=4 front-batched loads.
// R2 analysis: 268MB/35.5us = 7.56TB/s effective = ~94% of HBM spec; this is
// a wave-tail / launch-shape tweak at the roofline.

__device__ __forceinline__ float4 lwta4(float4 v) {
    float m = v.x; int idx = 0;
    if (v.y > m) { m = v.y; idx = 1; }
    if (v.z > m) { m = v.z; idx = 2; }
    if (v.w > m) { m = v.w; idx = 3; }
    float4 r;
    r.x = (idx == 0) ? v.x : 0.0f;
    r.y = (idx == 1) ? v.y : 0.0f;
    r.z = (idx == 2) ? v.z : 0.0f;
    r.w = (idx == 3) ? v.w : 0.0f;
    return r;
}

__global__ void __launch_bounds__(512) lwta_kernel(const float4* __restrict__ in,
                                                   float4* __restrict__ out,
                                                   int n_groups) {
    const int UNROLL = 4;
    const int BS = 512;
    int block_base = blockIdx.x * (BS * UNROLL);
    int tid = block_base + threadIdx.x;

    if (block_base + BS * UNROLL <= n_groups) {
        float4 a = __ldcs(&in[tid]);
        float4 b = __ldcs(&in[tid + BS]);
        float4 c = __ldcs(&in[tid + 2 * BS]);
        float4 d = __ldcs(&in[tid + 3 * BS]);
        __stcs(&out[tid],          lwta4(a));
        __stcs(&out[tid + BS],     lwta4(b));
        __stcs(&out[tid + 2 * BS], lwta4(c));
        __stcs(&out[tid + 3 * BS], lwta4(d));
    } else {
        #pragma unroll
        for (int k = 0; k < UNROLL; k++) {
            int i = tid + k * BS;
            if (i < n_groups)
                __stcs(&out[i], lwta4(__ldcs(&in[i])));
        }
    }
}

extern "C" void kernel_launch(void* const* d_in, const int* in_sizes, int n_in,
                              void* d_out, int out_size) {
    const float4* in = (const float4*)d_in[0];
    float4* out = (float4*)d_out;
    int n = in_sizes[0];              // 4096*8192 = 33554432 floats
    int n_groups = n / 4;             // 8388608 float4 groups
    int groups_per_block = 512 * 4;   // unroll 4, 512 threads
    int blocks = (n_groups + groups_per_block - 1) / groups_per_block;  // 4096
    lwta_kernel<<<blocks, 512>>>(in, out, n_groups);
}

// round 5
// speedup vs baseline: 1.0014x; 1.0014x over previous
#include <cuda_runtime.h>
#include <cstdint>

// LWTA over groups of 4 consecutive fp32 units. One float4 == one pool group.
// Keep first max (strict > matches jnp.argmax first-tie), zero rest.
//
// Final config (R2 revert): 256 threads, block-strided unroll-4. Every
// LDG.128/STG.128 fully coalesced (512B contiguous per warp), 4 front-batched
// loads per thread. Measured 35.5us kernel = 268MB @ ~7.56TB/s effective
// (~94% of 8TB/s HBM spec) — at the memory roofline.
// R3 (unroll 8): regs 27->40, occ down, slower. R4 (512-thread blocks):
// per-SM L1tex queue contention, slower. 256t x u4 is the TLP/MLP knee.

__device__ __forceinline__ float4 lwta4(float4 v) {
    float m = v.x; int idx = 0;
    if (v.y > m) { m = v.y; idx = 1; }
    if (v.z > m) { m = v.z; idx = 2; }
    if (v.w > m) { m = v.w; idx = 3; }
    float4 r;
    r.x = (idx == 0) ? v.x : 0.0f;
    r.y = (idx == 1) ? v.y : 0.0f;
    r.z = (idx == 2) ? v.z : 0.0f;
    r.w = (idx == 3) ? v.w : 0.0f;
    return r;
}

__global__ void __launch_bounds__(256) lwta_kernel(const float4* __restrict__ in,
                                                   float4* __restrict__ out,
                                                   int n_groups) {
    const int UNROLL = 4;
    const int BS = 256;
    int block_base = blockIdx.x * (BS * UNROLL);
    int tid = block_base + threadIdx.x;

    if (block_base + BS * UNROLL <= n_groups) {
        float4 v[UNROLL];
        #pragma unroll
        for (int k = 0; k < UNROLL; k++)
            v[k] = __ldcs(&in[tid + k * BS]);
        #pragma unroll
        for (int k = 0; k < UNROLL; k++)
            __stcs(&out[tid + k * BS], lwta4(v[k]));
    } else {
        #pragma unroll
        for (int k = 0; k < UNROLL; k++) {
            int i = tid + k * BS;
            if (i < n_groups)
                __stcs(&out[i], lwta4(__ldcs(&in[i])));
        }
    }
}

extern "C" void kernel_launch(void* const* d_in, const int* in_sizes, int n_in,
                              void* d_out, int out_size) {
    const float4* in = (const float4*)d_in[0];
    float4* out = (float4*)d_out;
    int n = in_sizes[0];              // 4096*8192 = 33554432 floats
    int n_groups = n / 4;             // 8388608 float4 groups
    int groups_per_block = 256 * 4;   // unroll 4
    int blocks = (n_groups + groups_per_block - 1) / groups_per_block;  // 8192
    lwta_kernel<<<blocks, 256>>>(in, out, n_groups);
}

// round 6
// speedup vs baseline: 1.0085x; 1.0071x over previous
#include <cuda_runtime.h>
#include <cstdint>

// LWTA over groups of 4 consecutive fp32 units. One float4 == one pool group.
// Keep first max (strict > matches jnp.argmax first-tie), zero rest.
//
// Config: 256 threads, two sequential unroll-4 phases per block.
//  - regs stay ~27 (only 4 float4 live at once) -> occ ~78% (R2 profile)
//  - grid = 4096 (R3 shape): half the block-scheduling events, exact cover
//  - every LDG.128/STG.128 fully coalesced (512B contiguous per warp)
// Measured roofline: 268MB mandatory traffic @ ~7.3-7.5TB/s effective ->
// kernel ~35.5us; this round targets the wave/launch tail only.

__device__ __forceinline__ float4 lwta4(float4 v) {
    float m = v.x; int idx = 0;
    if (v.y > m) { m = v.y; idx = 1; }
    if (v.z > m) { m = v.z; idx = 2; }
    if (v.w > m) { m = v.w; idx = 3; }
    float4 r;
    r.x = (idx == 0) ? v.x : 0.0f;
    r.y = (idx == 1) ? v.y : 0.0f;
    r.z = (idx == 2) ? v.z : 0.0f;
    r.w = (idx == 3) ? v.w : 0.0f;
    return r;
}

__global__ void __launch_bounds__(256) lwta_kernel(const float4* __restrict__ in,
                                                   float4* __restrict__ out,
                                                   int n_groups) {
    const int BS = 256;
    const int U = 4;
    const int PER_BLOCK = BS * U * 2;            // 2048 groups per block
    int block_base = blockIdx.x * PER_BLOCK;

    if (block_base + PER_BLOCK <= n_groups) {
        // phase 0
        int t0 = block_base + threadIdx.x;
        float4 v[U];
        #pragma unroll
        for (int k = 0; k < U; k++) v[k] = __ldcs(&in[t0 + k * BS]);
        #pragma unroll
        for (int k = 0; k < U; k++) __stcs(&out[t0 + k * BS], lwta4(v[k]));
        // phase 1
        int t1 = t0 + BS * U;
        #pragma unroll
        for (int k = 0; k < U; k++) v[k] = __ldcs(&in[t1 + k * BS]);
        #pragma unroll
        for (int k = 0; k < U; k++) __stcs(&out[t1 + k * BS], lwta4(v[k]));
    } else {
        #pragma unroll
        for (int k = 0; k < U * 2; k++) {
            int i = block_base + threadIdx.x + k * BS;
            if (i < n_groups)
                __stcs(&out[i], lwta4(__ldcs(&in[i])));
        }
    }
}

extern "C" void kernel_launch(void* const* d_in, const int* in_sizes, int n_in,
                              void* d_out, int out_size) {
    const float4* in = (const float4*)d_in[0];
    float4* out = (float4*)d_out;
    int n = in_sizes[0];               // 4096*8192 = 33554432 floats
    int n_groups = n / 4;              // 8388608 float4 groups
    int per_block = 256 * 4 * 2;       // 2048 groups per block
    int blocks = (n_groups + per_block - 1) / per_block;  // 4096
    lwta_kernel<<<blocks, 256>>>(in, out, n_groups);
}